// round 7
// baseline (speedup 1.0000x reference)
#include <cuda_runtime.h>

// Hausdorff distance, batched N=8, grid 96x96, coords (i/96, j/96).
// haus[s] = max(directed(A\B -> B), directed(B\A -> A)), out = mean over s.
// float4 loads -> nibble masks -> packed 96-bit row masks;
// row-EDT via clz/ffs; early-exit outward column scan (branchless, clamped).
// Grid (n, 2, 2): z splits phase-3 pixels in half for 2x SM coverage.

#define HD 96
#define WD 96
#define HW (HD * WD)
#define NWORDS (HW / 32)      // 288
#define NQUAD  (HW / 4)       // 2304
#define NT 1024
#define HALF (HW / 2)         // 4608 pixels per z-block

__device__ float        g_dir[64];     // [s*4 + dir*2 + z]
__device__ unsigned int g_count = 0;   // self-resetting last-block counter

static __device__ __forceinline__ unsigned pack_nib(unsigned x) {
    return (x & 0xFu) | ((x >> 4) & 0xF0u) | ((x >> 8) & 0xF00u) | ((x >> 12) & 0xF000u);
}

__global__ void __launch_bounds__(NT) hausdorff_kernel(
    const float* __restrict__ pred, const float* __restrict__ targ,
    float* __restrict__ out, int n) {
    __shared__ unsigned char  s_an[NQUAD];     // pred nibbles
    __shared__ unsigned char  s_bn[NQUAD];     // targ nibbles
    __shared__ unsigned int   s_tm[NWORDS];    // target row-mask words (per dir)
    __shared__ unsigned int   s_sw[NWORDS];    // source row-mask words (per dir)
    __shared__ unsigned short s_rd2[HW];       // squared row distance (sentinel 40000)
    __shared__ int s_red[32];

    const int s    = blockIdx.x;
    const int dir  = blockIdx.y;               // 0: tgt=B, src=A&~B ; 1: tgt=A, src=B&~A
    const int z    = blockIdx.z;               // pixel-half for phase 3
    const int tid  = threadIdx.x;
    const int lane = tid & 31;
    const int wrp  = tid >> 5;                 // 0..31

    const float4* __restrict__ P4 = (const float4*)(pred + s * HW);
    const float4* __restrict__ T4 = (const float4*)(targ + s * HW);

    // ---- Phase 1a: vectorized loads -> nibbles (round(x)>0.5 <=> x>0.5 on [0,1))
    #pragma unroll
    for (int k = 0; k < 3; k++) {
        int p = tid + k * NT;
        if (p < NQUAD) {
            float4 a = P4[p];
            float4 b = T4[p];
            unsigned na = (unsigned)(a.x > 0.5f) | ((unsigned)(a.y > 0.5f) << 1)
                        | ((unsigned)(a.z > 0.5f) << 2) | ((unsigned)(a.w > 0.5f) << 3);
            unsigned nb = (unsigned)(b.x > 0.5f) | ((unsigned)(b.y > 0.5f) << 1)
                        | ((unsigned)(b.z > 0.5f) << 2) | ((unsigned)(b.w > 0.5f) << 3);
            s_an[p] = (unsigned char)na;
            s_bn[p] = (unsigned char)nb;
        }
    }
    __syncthreads();

    // ---- Phase 1b: pack 8 nibbles -> mask words; build target + source words
    int myTgtNonzero = 0;
    if (tid < NWORDS) {
        const unsigned* pa = (const unsigned*)s_an;
        const unsigned* pb = (const unsigned*)s_bn;
        unsigned am = pack_nib(pa[2 * tid]) | (pack_nib(pa[2 * tid + 1]) << 16);
        unsigned bm = pack_nib(pb[2 * tid]) | (pack_nib(pb[2 * tid + 1]) << 16);
        unsigned tm = dir ? am : bm;
        unsigned sw = dir ? (bm & ~am) : (am & ~bm);
        s_tm[tid] = tm;
        s_sw[tid] = sw;
        myTgtNonzero = (tm != 0);
    }
    const int anyTgt = __syncthreads_or(myTgtNonzero);

    // ---- Phase 2: squared row distances. Warp w owns rows 3w..3w+2;
    // lane handles j = lane, lane+32, lane+64.
    #pragma unroll
    for (int rr = 0; rr < 3; rr++) {
        const int i = wrp * 3 + rr;
        const unsigned m0 = s_tm[i * 3], m1 = s_tm[i * 3 + 1], m2 = s_tm[i * 3 + 2];
        const unsigned long long lo = (unsigned long long)m0 | ((unsigned long long)m1 << 32);
        const unsigned hi = m2;
        int v0, v1, v2;
        {   // j = lane
            const int j = lane;
            unsigned long long x = lo & (~0ULL >> (63 - j));
            int dl = x ? (j - (63 - __clzll(x))) : 200;
            unsigned long long y = lo >> j;
            int dr = y ? (__ffsll(y) - 1) : (hi ? (64 - j) + __ffs(hi) - 1 : 200);
            v0 = min(dl, dr);
        }
        {   // j = lane+32
            const int j = lane + 32;
            unsigned long long x = lo & (~0ULL >> (63 - j));
            int dl = x ? (j - (63 - __clzll(x))) : 200;
            unsigned long long y = lo >> j;
            int dr = y ? (__ffsll(y) - 1) : (hi ? (64 - j) + __ffs(hi) - 1 : 200);
            v1 = min(dl, dr);
        }
        {   // j = lane+64
            const int j = lane + 64;
            unsigned x = hi & (~0u >> (31 - lane));
            int dl;
            if (x)       dl = j - (64 + 31 - __clz(x));
            else if (lo) dl = j - (63 - __clzll(lo));
            else         dl = 200;
            unsigned y = hi >> lane;
            int dr = y ? (__ffs(y) - 1) : 200;
            v2 = min(dl, dr);
        }
        s_rd2[i * WD + lane]      = (unsigned short)(v0 * v0);
        s_rd2[i * WD + lane + 32] = (unsigned short)(v1 * v1);
        s_rd2[i * WD + lane + 64] = (unsigned short)(v2 * v2);
    }
    __syncthreads();

    // ---- Phase 3: early-exit outward column scan on this block's pixel half.
    // Branchless: clamped boundary reads only over-estimate candidates that are
    // (or would be) evaluated exactly at smaller di, so the min is unchanged.
    int best = -1;
    #pragma unroll
    for (int k = 0; k < 5; k++) {
        const int off = tid + k * NT;
        if (off < HALF) {
            const int p = z * HALF + off;
            const int i = p / WD;
            const int j = p - i * WD;
            const unsigned sw = s_sw[p >> 5];            // warp-uniform broadcast
            int bst = ((sw >> lane) & 1u) ? (int)s_rd2[p] : -1;
            int d2 = 1;
            for (int di = 1; d2 < bst; d2 += 2 * di + 1, di++) {
                int u = max(i - di, 0) * WD + j;
                int v = min(i + di, HD - 1) * WD + j;
                bst = min(bst, d2 + (int)s_rd2[u]);
                bst = min(bst, d2 + (int)s_rd2[v]);
            }
            best = max(best, bst);
        }
    }

    // ---- Block max-reduction
    #pragma unroll
    for (int off = 16; off > 0; off >>= 1)
        best = max(best, __shfl_xor_sync(0xffffffffu, best, off));
    if (lane == 0) s_red[wrp] = best;
    __syncthreads();
    if (wrp == 0) {
        int m = s_red[lane];
        #pragma unroll
        for (int off = 16; off > 0; off >>= 1)
            m = max(m, __shfl_xor_sync(0xffffffffu, m, off));
        if (lane == 0) {
            float r;
            if (m < 0)        r = 0.0f;                  // this half's source set empty
            else if (!anyTgt) r = 1e9f;                  // src nonempty, tgt empty
            else              r = sqrtf((float)m) * (1.0f / 96.0f);
            g_dir[s * 4 + dir * 2 + z] = r;
            __threadfence();
            unsigned int t = atomicAdd(&g_count, 1);
            if (t == (unsigned int)(4 * n - 1)) {        // last block: finish + reset
                __threadfence();
                volatile float* gd = g_dir;
                float acc = 0.0f;
                for (int i = 0; i < n; i++) {
                    float h = fmaxf(fmaxf(gd[4 * i], gd[4 * i + 1]),
                                    fmaxf(gd[4 * i + 2], gd[4 * i + 3]));
                    acc += h;
                }
                out[0] = acc / (float)n;
                g_count = 0;                             // self-reset for next replay
            }
        }
    }
}

extern "C" void kernel_launch(void* const* d_in, const int* in_sizes, int n_in,
                              void* d_out, int out_size) {
    const float* pred = (const float*)d_in[0];
    const float* targ = (const float*)d_in[1];
    float* out = (float*)d_out;
    int n = in_sizes[0] / HW;   // batch size (8)

    dim3 grid(n, 2, 2);
    hausdorff_kernel<<<grid, NT>>>(pred, targ, out, n);
}